// round 2
// baseline (speedup 1.0000x reference)
#include <cuda_runtime.h>

// AUGRU: B=65536, T=50, E=10.
// Algebraic fold: (x@Wi + bi + h@Wh)@Ws + bs  ==  x@(Wi@Ws) + h@(Wh@Ws) + (bi@Ws + bs)
// Precompute kernel builds 6 folded 10x10 matrices (stored TRANSPOSED, row
// stride 16 floats for LDS.128 alignment) + 3 folded bias vectors into a
// __device__ scratch; main kernel stages them in smem and runs the recurrence
// with one thread per batch element.

#define AUGRU_E 10
#define AUGRU_T 50
#define AUGRU_B 65536
#define RSTRIDE 16   // floats per transposed-matrix row (pad 10 -> 16, 64B aligned)

// scratch: 6 matrices * 10 rows * 16 + 3 biases * 16 = 960 + 48 = 1008 floats
__device__ float g_augru_w[1008];

__global__ void augru_precompute(
    const float* __restrict__ Wi_r, const float* __restrict__ bi_r,
    const float* __restrict__ Wh_r, const float* __restrict__ Ws_r, const float* __restrict__ bs_r,
    const float* __restrict__ Wi_z, const float* __restrict__ bi_z,
    const float* __restrict__ Wh_z, const float* __restrict__ Ws_z, const float* __restrict__ bs_z,
    const float* __restrict__ Wi_h, const float* __restrict__ bi_h,
    const float* __restrict__ Wh_h, const float* __restrict__ Wt_h, const float* __restrict__ bt_h)
{
    int tid = threadIdx.x;
    if (tid < 600) {
        // matrix entries: m in 0..5 selects (W1,W2); A = W1 @ W2, store A^T[j][k]
        int m = tid / 100, rem = tid % 100, j = rem / 10, k = rem % 10;
        const float* W1; const float* W2;
        switch (m) {
            case 0: W1 = Wi_r; W2 = Ws_r; break;   // Axr
            case 1: W1 = Wh_r; W2 = Ws_r; break;   // Ahr
            case 2: W1 = Wi_z; W2 = Ws_z; break;   // Axz
            case 3: W1 = Wh_z; W2 = Ws_z; break;   // Ahz
            case 4: W1 = Wi_h; W2 = Wt_h; break;   // Axh
            default: W1 = Wh_h; W2 = Wt_h; break;  // Ahh
        }
        float acc = 0.f;
        #pragma unroll
        for (int mm = 0; mm < AUGRU_E; mm++)
            acc += W1[k * AUGRU_E + mm] * W2[mm * AUGRU_E + j];
        g_augru_w[m * 160 + j * RSTRIDE + k] = acc;
    } else if (tid < 630) {
        // folded biases: c[j] = sum_m bi[m]*Ws[m][j] + bs[j]
        int b = (tid - 600) / 10, j = (tid - 600) % 10;
        const float* bi; const float* Ws; const float* bs;
        if (b == 0)      { bi = bi_r; Ws = Ws_r; bs = bs_r; }
        else if (b == 1) { bi = bi_z; Ws = Ws_z; bs = bs_z; }
        else             { bi = bi_h; Ws = Wt_h; bs = bt_h; }
        float acc = bs[j];
        #pragma unroll
        for (int mm = 0; mm < AUGRU_E; mm++)
            acc += bi[mm] * Ws[mm * AUGRU_E + j];
        g_augru_w[960 + b * RSTRIDE + j] = acc;
    }
}

__device__ __forceinline__ float fast_sigmoid(float x) {
    return __fdividef(1.f, 1.f + __expf(-x));
}
__device__ __forceinline__ float fast_tanh(float x) {
    float e = __expf(-2.f * x);
    return __fdividef(1.f - e, 1.f + e);
}

// dot of a 10-wide smem row (16B-aligned, LDS.128-friendly) with a register vector
__device__ __forceinline__ float dot10(const float* __restrict__ row, const float* __restrict__ v) {
    float4 w0 = *reinterpret_cast<const float4*>(row);
    float4 w1 = *reinterpret_cast<const float4*>(row + 4);
    float2 w2 = *reinterpret_cast<const float2*>(row + 8);
    float s = w0.x * v[0];
    s = fmaf(w0.y, v[1], s);
    s = fmaf(w0.z, v[2], s);
    s = fmaf(w0.w, v[3], s);
    s = fmaf(w1.x, v[4], s);
    s = fmaf(w1.y, v[5], s);
    s = fmaf(w1.z, v[6], s);
    s = fmaf(w1.w, v[7], s);
    s = fmaf(w2.x, v[8], s);
    s = fmaf(w2.y, v[9], s);
    return s;
}

__global__ void __launch_bounds__(64) augru_main(
    const float* __restrict__ gx,   // [B, T, E]
    const float* __restrict__ ga,   // [B, T, E]
    const float* __restrict__ h0,   // [1, E]
    float* __restrict__ out)        // [B, E]
{
    __shared__ __align__(16) float sw[1008];
    for (int i = threadIdx.x; i < 1008; i += 64) sw[i] = g_augru_w[i];
    __syncthreads();

    const float* Axr = sw + 0;
    const float* Ahr = sw + 160;
    const float* Axz = sw + 320;
    const float* Ahz = sw + 480;
    const float* Axh = sw + 640;
    const float* Ahh = sw + 800;
    const float* cr  = sw + 960;
    const float* cz  = sw + 976;
    const float* ch  = sw + 992;

    const int b = blockIdx.x * 64 + threadIdx.x;

    float h[AUGRU_E];
    #pragma unroll
    for (int j = 0; j < AUGRU_E; j++) h[j] = h0[j];

    const float2* __restrict__ px =
        reinterpret_cast<const float2*>(gx) + (size_t)b * (AUGRU_T * AUGRU_E / 2);
    const float2* __restrict__ pa =
        reinterpret_cast<const float2*>(ga) + (size_t)b * (AUGRU_T * AUGRU_E / 2);

    #pragma unroll 1
    for (int t = 0; t < AUGRU_T; t++) {
        float x[AUGRU_E];
        #pragma unroll
        for (int i = 0; i < 5; i++) {
            float2 v = px[t * 5 + i];
            x[2 * i] = v.x; x[2 * i + 1] = v.y;
        }

        float rp[AUGRU_E], zp[AUGRU_E];
        #pragma unroll
        for (int j = 0; j < AUGRU_E; j++) {
            rp[j] = cr[j] + dot10(Axr + j * RSTRIDE, x) + dot10(Ahr + j * RSTRIDE, h);
            zp[j] = cz[j] + dot10(Axz + j * RSTRIDE, x) + dot10(Ahz + j * RSTRIDE, h);
        }

        float hz[AUGRU_E];
        #pragma unroll
        for (int j = 0; j < AUGRU_E; j++)
            hz[j] = h[j] * fast_sigmoid(zp[j]);

        float hcp[AUGRU_E];
        #pragma unroll
        for (int j = 0; j < AUGRU_E; j++)
            hcp[j] = ch[j] + dot10(Axh + j * RSTRIDE, x) + dot10(Ahh + j * RSTRIDE, hz);

        float a[AUGRU_E];
        #pragma unroll
        for (int i = 0; i < 5; i++) {
            float2 v = pa[t * 5 + i];
            a[2 * i] = v.x; a[2 * i + 1] = v.y;
        }

        #pragma unroll
        for (int j = 0; j < AUGRU_E; j++) {
            float Ra = a[j] * fast_sigmoid(rp[j]);
            float hc = fast_tanh(hcp[j]);
            h[j] = fmaf(Ra, hc - h[j], h[j]);   // (1-Ra)*h + Ra*hc
        }
    }

    float2* __restrict__ po = reinterpret_cast<float2*>(out) + (size_t)b * (AUGRU_E / 2);
    #pragma unroll
    for (int i = 0; i < 5; i++) {
        float2 v;
        v.x = h[2 * i]; v.y = h[2 * i + 1];
        po[i] = v;
    }
}

extern "C" void kernel_launch(void* const* d_in, const int* in_sizes, int n_in,
                              void* d_out, int out_size) {
    const float* gx   = (const float*)d_in[0];   // gru_hidden_state_inputs
    const float* ga   = (const float*)d_in[1];   // attention_s
    const float* h0   = (const float*)d_in[2];
    const float* Wi_r = (const float*)d_in[3];
    const float* bi_r = (const float*)d_in[4];
    const float* Wh_r = (const float*)d_in[5];
    const float* Ws_r = (const float*)d_in[6];
    const float* bs_r = (const float*)d_in[7];
    const float* Wi_z = (const float*)d_in[8];
    const float* bi_z = (const float*)d_in[9];
    const float* Wh_z = (const float*)d_in[10];
    const float* Ws_z = (const float*)d_in[11];
    const float* bs_z = (const float*)d_in[12];
    const float* Wi_h = (const float*)d_in[13];
    const float* bi_h = (const float*)d_in[14];
    const float* Wh_h = (const float*)d_in[15];
    const float* Wt_h = (const float*)d_in[16];
    const float* bt_h = (const float*)d_in[17];
    float* out = (float*)d_out;

    augru_precompute<<<1, 640>>>(Wi_r, bi_r, Wh_r, Ws_r, bs_r,
                                 Wi_z, bi_z, Wh_z, Ws_z, bs_z,
                                 Wi_h, bi_h, Wh_h, Wt_h, bt_h);
    augru_main<<<AUGRU_B / 64, 64>>>(gx, ga, h0, out);
}

// round 3
// speedup vs baseline: 12.8139x; 12.8139x over previous
#include <cuda_runtime.h>
#include <cstdint>

// AUGRU: B=65536, T=50, E=10.
// Fold: (x@Wi + bi + h@Wh)@Ws + bs == x@(Wi@Ws) + h@(Wh@Ws) + (bi@Ws + bs)
// Main kernel: 32 threads/block, each thread owns TWO batch rows (tid, tid+32),
// computed in packed f32x2 (fma.rn.f32x2). Inputs staged through smem with
// double-buffered cp.async for coalesced DRAM access. Weights pair-duplicated
// in smem so LDS.128 feeds packed FFMA2 directly.

#define E_  10
#define T_  50
#define B_  65536
#define NB  32          // threads per block
#define EB  64          // batch elems per block
#define RS  10          // floats staged per row per chunk (1 timestep)
#define ROWB (T_*E_)    // 500 floats per batch row

// folded weights, pair-duplicated: 6 mats * 10j * 20 + 3 biases * 20 = 1260
__device__ float g_w2[1280];

__global__ void augru_precompute(
    const float* __restrict__ Wi_r, const float* __restrict__ bi_r,
    const float* __restrict__ Wh_r, const float* __restrict__ Ws_r, const float* __restrict__ bs_r,
    const float* __restrict__ Wi_z, const float* __restrict__ bi_z,
    const float* __restrict__ Wh_z, const float* __restrict__ Ws_z, const float* __restrict__ bs_z,
    const float* __restrict__ Wi_h, const float* __restrict__ bi_h,
    const float* __restrict__ Wh_h, const float* __restrict__ Wt_h, const float* __restrict__ bt_h)
{
    int tid = threadIdx.x;
    if (tid < 600) {
        int m = tid / 100, rem = tid % 100, j = rem / 10, k = rem % 10;
        const float* W1; const float* W2;
        switch (m) {
            case 0: W1 = Wi_r; W2 = Ws_r; break;
            case 1: W1 = Wh_r; W2 = Ws_r; break;
            case 2: W1 = Wi_z; W2 = Ws_z; break;
            case 3: W1 = Wh_z; W2 = Ws_z; break;
            case 4: W1 = Wi_h; W2 = Wt_h; break;
            default: W1 = Wh_h; W2 = Wt_h; break;
        }
        float acc = 0.f;
        #pragma unroll
        for (int mm = 0; mm < E_; mm++)
            acc += W1[k * E_ + mm] * W2[mm * E_ + j];
        g_w2[m * 200 + j * 20 + 2 * k]     = acc;   // duplicated pair for f32x2
        g_w2[m * 200 + j * 20 + 2 * k + 1] = acc;
    } else if (tid < 630) {
        int g = (tid - 600) / 10, j = (tid - 600) % 10;
        const float* bi; const float* Ws; const float* bs;
        if (g == 0)      { bi = bi_r; Ws = Ws_r; bs = bs_r; }
        else if (g == 1) { bi = bi_z; Ws = Ws_z; bs = bs_z; }
        else             { bi = bi_h; Ws = Wt_h; bs = bt_h; }
        float acc = bs[j];
        #pragma unroll
        for (int mm = 0; mm < E_; mm++)
            acc += bi[mm] * Ws[mm * E_ + j];
        g_w2[1200 + g * 20 + 2 * j]     = acc;
        g_w2[1200 + g * 20 + 2 * j + 1] = acc;
    }
}

__device__ __forceinline__ float2 fma2(float2 a, float2 b, float2 c) {
    unsigned long long ua = *reinterpret_cast<unsigned long long*>(&a);
    unsigned long long ub = *reinterpret_cast<unsigned long long*>(&b);
    unsigned long long uc = *reinterpret_cast<unsigned long long*>(&c);
    unsigned long long ud;
    asm("fma.rn.f32x2 %0, %1, %2, %3;" : "=l"(ud) : "l"(ua), "l"(ub), "l"(uc));
    return *reinterpret_cast<float2*>(&ud);
}

__device__ __forceinline__ float sigf(float x) {
    return __fdividef(1.f, 1.f + __expf(-x));
}
__device__ __forceinline__ float tanhf_(float x) {
    float e = __expf(-2.f * x);
    return __fdividef(1.f - e, 1.f + e);
}

// accumulate 10-wide packed dot: wrow = pair-duplicated weights (5 x float4),
// v = 10 packed (batch-pair) values
__device__ __forceinline__ float2 dotacc(const float4* __restrict__ wrow,
                                         const float2* __restrict__ v, float2 acc) {
    #pragma unroll
    for (int i = 0; i < 5; i++) {
        float4 q = wrow[i];
        acc = fma2(*reinterpret_cast<const float2*>(&q.x), v[2 * i],     acc);
        acc = fma2(*reinterpret_cast<const float2*>(&q.z), v[2 * i + 1], acc);
    }
    return acc;
}

__device__ __forceinline__ void cpa8(uint32_t smem_addr, const void* gptr) {
    asm volatile("cp.async.ca.shared.global [%0], [%1], 8;" :: "r"(smem_addr), "l"(gptr));
}

__global__ void __launch_bounds__(NB) augru_main(
    const float* __restrict__ gx,   // [B, T, E]
    const float* __restrict__ ga,   // [B, T, E]
    const float* __restrict__ h0,   // [1, E]
    float* __restrict__ out)        // [B, E]
{
    __shared__ __align__(16) float sw[1280];
    __shared__ __align__(16) float sx[2][EB * RS];   // [buf][row][10]
    __shared__ __align__(16) float sa[2][EB * RS];

    const int tid = threadIdx.x;
    const int b0  = blockIdx.x * EB;

    const uint32_t sxa = (uint32_t)__cvta_generic_to_shared(&sx[0][0]);
    const uint32_t saa = (uint32_t)__cvta_generic_to_shared(&sa[0][0]);
    const char* gxb = (const char*)gx + (size_t)b0 * (ROWB * 4);
    const char* gab = (const char*)ga + (size_t)b0 * (ROWB * 4);

    // stage timestep t into buffer d: 64 rows x 40B each, 5 x 8B per row
    auto stage = [&](int t, int d) {
        const char* px = gxb + t * (RS * 4);
        const char* pa = gab + t * (RS * 4);
        #pragma unroll
        for (int i = 0; i < 10; i++) {
            int idx = tid + i * NB;        // 0..319
            int r = idx / 5, c = idx % 5;
            uint32_t soff = (uint32_t)((d * (EB * RS) + r * RS + c * 2) * 4);
            size_t goff = (size_t)r * (ROWB * 4) + c * 8;
            cpa8(sxa + soff, px + goff);
            cpa8(saa + soff, pa + goff);
        }
        asm volatile("cp.async.commit_group;");
    };

    // kick off first stage before anything else
    stage(0, 0);

    // load weights (broadcast later via LDS)
    for (int i = tid; i < 1280; i += NB) sw[i] = g_w2[i];

    // init h packed: lane handles elems (b0+tid, b0+tid+32), same h0
    float2 h[E_];
    #pragma unroll
    for (int j = 0; j < E_; j++) h[j] = make_float2(h0[j], h0[j]);

    __syncwarp();   // weights visible

    #pragma unroll 1
    for (int t = 0; t < T_; t++) {
        const int d = t & 1;
        if (t + 1 < T_) {
            stage(t + 1, d ^ 1);
            asm volatile("cp.async.wait_group 1;");
        } else {
            asm volatile("cp.async.wait_group 0;");
        }
        __syncwarp();

        const float* __restrict__ xb = &sx[d][0];
        const float* __restrict__ ab = &sa[d][0];

        // pack x: (row tid, row tid+32) feature k
        float2 xp[E_];
        #pragma unroll
        for (int k = 0; k < E_; k++)
            xp[k] = make_float2(xb[tid * RS + k], xb[(tid + NB) * RS + k]);

        // r pre-activation (kept for epilogue)
        float2 rp[E_];
        #pragma unroll
        for (int j = 0; j < E_; j++) {
            float2 acc = *reinterpret_cast<const float2*>(sw + 1200 + 2 * j);
            acc = dotacc(reinterpret_cast<const float4*>(sw + 0 * 200 + j * 20), xp, acc);
            acc = dotacc(reinterpret_cast<const float4*>(sw + 1 * 200 + j * 20), h,  acc);
            rp[j] = acc;
        }

        // z gate -> h*z
        float2 hz[E_];
        #pragma unroll
        for (int j = 0; j < E_; j++) {
            float2 acc = *reinterpret_cast<const float2*>(sw + 1200 + 20 + 2 * j);
            acc = dotacc(reinterpret_cast<const float4*>(sw + 2 * 200 + j * 20), xp, acc);
            acc = dotacc(reinterpret_cast<const float4*>(sw + 3 * 200 + j * 20), h,  acc);
            hz[j] = make_float2(h[j].x * sigf(acc.x), h[j].y * sigf(acc.y));
        }

        // candidate + epilogue
        #pragma unroll
        for (int j = 0; j < E_; j++) {
            float2 acc = *reinterpret_cast<const float2*>(sw + 1200 + 40 + 2 * j);
            acc = dotacc(reinterpret_cast<const float4*>(sw + 4 * 200 + j * 20), xp, acc);
            acc = dotacc(reinterpret_cast<const float4*>(sw + 5 * 200 + j * 20), hz, acc);
            float hcl = tanhf_(acc.x), hch = tanhf_(acc.y);
            float srl = sigf(rp[j].x), srh = sigf(rp[j].y);
            float al = ab[tid * RS + j], ah = ab[(tid + NB) * RS + j];
            float Ral = al * srl, Rah = ah * srh;
            h[j].x = fmaf(Ral, hcl - h[j].x, h[j].x);
            h[j].y = fmaf(Rah, hch - h[j].y, h[j].y);
        }

        __syncwarp();   // everyone done reading buf d before it is re-staged
    }

    // write out: elem rows b0+tid and b0+tid+32, 5 float2 each
    float2* __restrict__ po = reinterpret_cast<float2*>(out);
    #pragma unroll
    for (int i = 0; i < 5; i++) {
        po[(size_t)(b0 + tid) * 5 + i]      = make_float2(h[2 * i].x, h[2 * i + 1].x);
        po[(size_t)(b0 + tid + NB) * 5 + i] = make_float2(h[2 * i].y, h[2 * i + 1].y);
    }
}

extern "C" void kernel_launch(void* const* d_in, const int* in_sizes, int n_in,
                              void* d_out, int out_size) {
    const float* gx   = (const float*)d_in[0];
    const float* ga   = (const float*)d_in[1];
    const float* h0   = (const float*)d_in[2];
    const float* Wi_r = (const float*)d_in[3];
    const float* bi_r = (const float*)d_in[4];
    const float* Wh_r = (const float*)d_in[5];
    const float* Ws_r = (const float*)d_in[6];
    const float* bs_r = (const float*)d_in[7];
    const float* Wi_z = (const float*)d_in[8];
    const float* bi_z = (const float*)d_in[9];
    const float* Wh_z = (const float*)d_in[10];
    const float* Ws_z = (const float*)d_in[11];
    const float* bs_z = (const float*)d_in[12];
    const float* Wi_h = (const float*)d_in[13];
    const float* bi_h = (const float*)d_in[14];
    const float* Wh_h = (const float*)d_in[15];
    const float* Wt_h = (const float*)d_in[16];
    const float* bt_h = (const float*)d_in[17];
    float* out = (float*)d_out;

    augru_precompute<<<1, 640>>>(Wi_r, bi_r, Wh_r, Ws_r, bs_r,
                                 Wi_z, bi_z, Wh_z, Ws_z, bs_z,
                                 Wi_h, bi_h, Wh_h, Wt_h, bt_h);
    augru_main<<<B_ / EB, NB>>>(gx, ga, h0, out);
}